// round 5
// baseline (speedup 1.0000x reference)
#include <cuda_runtime.h>
#include <cuda_bf16.h>
#include <math.h>

// out [16,4096,513] f32 flat = 33,619,968 floats = 8,404,992 float4s.
// Aligned float4 stores over flat output; scalar loads dedup'd via L2 sectors.
// Unroll 4: 256-thread CTAs, 4 coalesced float4s per thread, loads front-batched.
// grid = 8,404,992 / (256*4) = 8208 CTAs exactly.

#define S_DIM 4096
#define D_DIM 512
#define OD    513u
#define PI_F 3.14159265358979323846f
#define UNROLL 4

__device__ __forceinline__ float pe_val(unsigned row, const int* __restrict__ lengths) {
    const unsigned b = row >> 12;
    const unsigned s = row & (S_DIM - 1);
    const int len = __ldg(&lengths[b]);
    float pe = 0.0f;
    if ((int)s < len) {
        float fl = fmaxf((float)len, 1.0f);
        pe = cosf((float)s / fl * PI_F);
    }
    return pe;
}

__device__ __forceinline__ float4 gather4(unsigned idx,
                                          const float* __restrict__ inp,
                                          const int* __restrict__ lengths) {
    const unsigned f   = idx * 4u;
    const unsigned row = f / OD;            // mulhi
    const unsigned col = f - row * OD;
    float4 v;
    if (col <= (unsigned)(D_DIM - 4)) {
        const float* src = inp + (size_t)row * D_DIM + col;
        v.x = __ldcs(src + 0);
        v.y = __ldcs(src + 1);
        v.z = __ldcs(src + 2);
        v.w = __ldcs(src + 3);
    } else {
        float tmp[4];
        #pragma unroll
        for (int k = 0; k < 4; k++) {
            unsigned ck = col + (unsigned)k;
            if (ck < (unsigned)D_DIM) {
                tmp[k] = __ldcs(inp + (size_t)row * D_DIM + ck);
            } else if (ck == (unsigned)D_DIM) {
                tmp[k] = pe_val(row, lengths);
            } else {
                tmp[k] = __ldcs(inp + (size_t)(row + 1u) * D_DIM + (ck - OD));
            }
        }
        v.x = tmp[0]; v.y = tmp[1]; v.z = tmp[2]; v.w = tmp[3];
    }
    return v;
}

__global__ __launch_bounds__(256) void concat_pe_u4_kernel(
    const float* __restrict__ inp,
    const int* __restrict__ lengths,
    float* __restrict__ out)
{
    const unsigned base = blockIdx.x * (256u * UNROLL) + threadIdx.x;

    float4 v[UNROLL];
    #pragma unroll
    for (int k = 0; k < UNROLL; k++)
        v[k] = gather4(base + k * 256u, inp, lengths);

    float4* o = reinterpret_cast<float4*>(out);
    #pragma unroll
    for (int k = 0; k < UNROLL; k++)
        __stcs(o + base + k * 256u, v[k]);
}

extern "C" void kernel_launch(void* const* d_in, const int* in_sizes, int n_in,
                              void* d_out, int out_size) {
    const float* inp = (const float*)d_in[0];
    const int* lengths = (const int*)d_in[1];
    float* out = (float*)d_out;

    // 8,404,992 float4s / (256 threads * 4) = 8208 CTAs exactly.
    dim3 grid(8208);
    dim3 block(256);
    concat_pe_u4_kernel<<<grid, block>>>(inp, lengths, out);
}